// round 7
// baseline (speedup 1.0000x reference)
#include <cuda_runtime.h>
#include <stdint.h>

// ---------------------------------------------------------------------------
// AttentionDecoder_2035814499129  —  R6  (revert R5 tail, add REDUX reduce)
//
// choice   = argmax over valid i of gumbel(key(1))[i]; gumbel transform is
//            strictly monotone in (threefry_bits >> 9), so argmax the raw
//            23-bit values (identical ordering AND first-index tie-break).
// log_prob = -log(n_valid).
// PRNG: jax partitionable stream — bits[i] = x0^x1 of
//       threefry2x32(key=(0,1), counter=(0, i)).   (bit-exact since R2)
// Mask: int32 0/1.
//
// R6: (a) warp/cta reductions via REDUX max/min pairs (2 ops) instead of
// 10 dependent 32-bit SHFLs; (b) R4's REDG-based publish (non-final blocks
// never wait on an atomic round-trip); (c) last block reads g_best/g_count
// with two overlapped volatile loads instead of two serial ATOMGs.
// ---------------------------------------------------------------------------

__device__ unsigned long long g_best  = 0ULL;  // (bits23 << 32) | ~index
__device__ unsigned int       g_count = 0;
__device__ unsigned int       g_done  = 0;

__device__ __forceinline__ uint32_t rotl32(uint32_t x, int r) {
    return (x << r) | (x >> (32 - r));
}

// threefry2x32, key=(0,1); returns x0^x1 (jax partitionable 32-bit combine)
__device__ __forceinline__ uint32_t threefry_bits_key01(uint32_t x0, uint32_t x1) {
    const uint32_t ks0 = 0u, ks1 = 1u, ks2 = 0x1BD11BDBu;
    x0 += ks0; x1 += ks1;
#define TF_RND(r) { x0 += x1; x1 = rotl32(x1, (r)); x1 ^= x0; }
    TF_RND(13) TF_RND(15) TF_RND(26) TF_RND(6)
    x0 += ks1; x1 += ks2 + 1u;
    TF_RND(17) TF_RND(29) TF_RND(16) TF_RND(24)
    x0 += ks2; x1 += ks0 + 2u;
    TF_RND(13) TF_RND(15) TF_RND(26) TF_RND(6)
    x0 += ks0; x1 += ks1 + 3u;
    TF_RND(17) TF_RND(29) TF_RND(16) TF_RND(24)
    x0 += ks1; x1 += ks2 + 4u;
    TF_RND(13) TF_RND(15) TF_RND(26) TF_RND(6)
    x0 += ks2; x1 += ks0 + 5u;
#undef TF_RND
    return x0 ^ x1;
}

__global__ void __launch_bounds__(256)
decide_kernel(const int4* __restrict__ v4, const int* __restrict__ v,
              float* __restrict__ out, int n, int nblocks) {
    const int tid = threadIdx.x;
    const int gi  = blockIdx.x * blockDim.x + tid;
    const int n4  = n >> 2;

    // per-thread best as (value, min-index) pair
    uint32_t bv = 0u;            // bits23 value (0 = neutral)
    uint32_t bi = 0xFFFFFFFFu;   // index (sentinel = none)
    int cnt = 0;

    if (gi < n4) {
        int4 m = v4[gi];                       // load first; latency hidden below
        const uint32_t i0 = (uint32_t)(gi << 2);
        // 4 independent chains, no dependence on m -> overlap with the load
        uint32_t b0 = threefry_bits_key01(0u, i0     ) >> 9;
        uint32_t b1 = threefry_bits_key01(0u, i0 + 1u) >> 9;
        uint32_t b2 = threefry_bits_key01(0u, i0 + 2u) >> 9;
        uint32_t b3 = threefry_bits_key01(0u, i0 + 3u) >> 9;
        // +1 lifts valid values above the neutral 0; invalid -> 0
        b0 = m.x ? b0 + 1u : 0u;
        b1 = m.y ? b1 + 1u : 0u;
        b2 = m.z ? b2 + 1u : 0u;
        b3 = m.w ? b3 + 1u : 0u;
        // in-order scan keeps first-occurrence tie-break (strict >)
        bv = b0; bi = i0;
        if (b1 > bv) { bv = b1; bi = i0 + 1u; }
        if (b2 > bv) { bv = b2; bi = i0 + 2u; }
        if (b3 > bv) { bv = b3; bi = i0 + 3u; }
        cnt = m.x + m.y + m.z + m.w;           // mask words are exactly 0/1
    }
    // tail (n % 4 != 0 only; N=100000 -> dead, kept for generality)
    if (gi < (n & 3)) {
        uint32_t i = (uint32_t)((n4 << 2) + gi);
        if (v[i]) { cnt++; uint32_t b = (threefry_bits_key01(0u, i) >> 9) + 1u;
                    if (b > bv) { bv = b; bi = i; } }
    }

    // ---- warp reduction: 2 REDUX ops + 1 REDUX add ----
    cnt = __reduce_add_sync(0xFFFFFFFFu, (unsigned)cnt);
    uint32_t wmax = __reduce_max_sync(0xFFFFFFFFu, bv);
    uint32_t widx = __reduce_min_sync(0xFFFFFFFFu, (bv == wmax) ? bi : 0xFFFFFFFFu);

    // ---- cross-warp: 8 warps -> warp 0 ----
    __shared__ uint32_t sv[8], si[8];
    __shared__ int      sc[8];
    const int warp = tid >> 5, lane = tid & 31;
    if (lane == 0) { sv[warp] = wmax; si[warp] = widx; sc[warp] = cnt; }
    __syncthreads();
    if (warp == 0 && lane == 0) { /* placeholder to keep warp0 shape */ }
    if (warp == 0) {
        uint32_t v0 = (lane < 8) ? sv[lane] : 0u;
        uint32_t i0w = (lane < 8) ? si[lane] : 0xFFFFFFFFu;
        int      c0 = (lane < 8) ? sc[lane] : 0;
        c0 = __reduce_add_sync(0xFFFFFFFFu, (unsigned)c0);
        uint32_t bmax = __reduce_max_sync(0xFFFFFFFFu, v0);
        uint32_t bidx = __reduce_min_sync(0xFFFFFFFFu, (v0 == bmax) ? i0w : 0xFFFFFFFFu);

        if (lane == 0) {
            // encode (value, min-index) for a single global 64-bit max
            unsigned long long key =
                ((unsigned long long)bmax << 32) | (unsigned long long)(~bidx);
            atomicMax(&g_best, key);            // result unused -> REDG.MAX
            atomicAdd(&g_count, (unsigned)c0);  // result unused -> REDG.ADD
            __threadfence();                    // release before done++
            unsigned int t = atomicAdd(&g_done, 1u);
            if (t == (unsigned int)(nblocks - 1)) {
                __threadfence();                // acquire
                // two independent volatile loads (overlapped ~260cyc, not 2x318)
                unsigned long long fb = *(volatile unsigned long long*)&g_best;
                unsigned int       fc = *(volatile unsigned int*)&g_count;
                uint32_t choice = ~((uint32_t)(fb & 0xFFFFFFFFu));
                out[0] = (float)choice;
                out[1] = -__logf((float)(fc > 0u ? fc : 1u));
                g_best  = 0ULL;                 // reset for next graph replay
                g_count = 0u;
                g_done  = 0u;
            }
        }
    }
}

extern "C" void kernel_launch(void* const* d_in, const int* in_sizes, int n_in,
                              void* d_out, int out_size) {
    // inputs: ... 9 = valid_mask (int32), 10 = current_node
    const int* valid = (const int*)d_in[9];
    int n = in_sizes[9];                       // N = 100000
    int n4 = n >> 2;
    int threads = 256;
    int blocks = (n4 + threads - 1) / threads; // 98 for N=100000
    if (blocks < 1) blocks = 1;
    decide_kernel<<<blocks, threads>>>((const int4*)valid, valid,
                                       (float*)d_out, n, blocks);
}

// round 8
// speedup vs baseline: 1.3204x; 1.3204x over previous
#include <cuda_runtime.h>
#include <stdint.h>

// ---------------------------------------------------------------------------
// AttentionDecoder_2035814499129  —  R7  (R4 structure, tail micro-fixes)
//
// choice   = argmax over valid i of gumbel(key(1))[i]; the gumbel transform is
//            strictly monotone in (threefry_bits >> 9), so we argmax the raw
//            23-bit values (identical ordering AND first-index tie-break).
// log_prob = -log(n_valid).
// PRNG: jax partitionable stream — bits[i] = x0^x1 of
//       threefry2x32(key=(0,1), counter=(0, i)).   (bit-exact since R2)
// Mask: int32 0/1.
//
// R7 = R4 (best measured e2e 6.624) + two validated tail deltas:
//   * logf -> __logf                       (rel_err 8.8e-8, validated R5/R6)
//   * last-block readback: 2 overlapped volatile loads instead of 2 serial
//     ATOMG round-trips                    (validated correct in R6)
// Everything else byte-for-byte R4: u64 shuffle-max reduction (parallel
// two-SHFL tree beat the serial REDUX max->sel->min chain in measurement),
// REDG-only publish for non-final blocks.
// ---------------------------------------------------------------------------

__device__ unsigned long long g_best  = 0ULL;  // (bits23 << 32) | ~index
__device__ unsigned int       g_count = 0;
__device__ unsigned int       g_done  = 0;

__device__ __forceinline__ uint32_t rotl32(uint32_t x, int r) {
    return (x << r) | (x >> (32 - r));
}

// threefry2x32, key=(0,1); returns x0^x1 (jax partitionable 32-bit combine)
__device__ __forceinline__ uint32_t threefry_bits_key01(uint32_t x0, uint32_t x1) {
    const uint32_t ks0 = 0u, ks1 = 1u, ks2 = 0x1BD11BDBu;
    x0 += ks0; x1 += ks1;
#define TF_RND(r) { x0 += x1; x1 = rotl32(x1, (r)); x1 ^= x0; }
    TF_RND(13) TF_RND(15) TF_RND(26) TF_RND(6)
    x0 += ks1; x1 += ks2 + 1u;
    TF_RND(17) TF_RND(29) TF_RND(16) TF_RND(24)
    x0 += ks2; x1 += ks0 + 2u;
    TF_RND(13) TF_RND(15) TF_RND(26) TF_RND(6)
    x0 += ks0; x1 += ks1 + 3u;
    TF_RND(17) TF_RND(29) TF_RND(16) TF_RND(24)
    x0 += ks1; x1 += ks2 + 4u;
    TF_RND(13) TF_RND(15) TF_RND(26) TF_RND(6)
    x0 += ks2; x1 += ks0 + 5u;
#undef TF_RND
    return x0 ^ x1;
}

// (bits>>9) is monotone-equivalent to the gumbel value; ~idx gives
// first-occurrence tie-break under 64-bit max.
__device__ __forceinline__ unsigned long long enc_from_bits(uint32_t bits, uint32_t idx) {
    return ((unsigned long long)(bits >> 9) << 32)
         | (unsigned long long)(0xFFFFFFFFu - idx);
}

__device__ __forceinline__ unsigned long long u64max(unsigned long long a,
                                                     unsigned long long b) {
    return a > b ? a : b;
}

__global__ void __launch_bounds__(256)
decide_kernel(const int4* __restrict__ v4, const int* __restrict__ v,
              float* __restrict__ out, int n, int nblocks) {
    const int tid = threadIdx.x;
    const int gi  = blockIdx.x * blockDim.x + tid;
    const int n4  = n >> 2;

    unsigned long long best = 0ULL;
    int cnt = 0;

    if (gi < n4) {
        int4 m = v4[gi];                       // issued first; latency hidden below
        const uint32_t i0 = (uint32_t)(gi << 2);
        // 4 independent chains, NO dependence on m -> overlap with the load
        unsigned long long k0 = enc_from_bits(threefry_bits_key01(0u, i0     ), i0     );
        unsigned long long k1 = enc_from_bits(threefry_bits_key01(0u, i0 + 1u), i0 + 1u);
        unsigned long long k2 = enc_from_bits(threefry_bits_key01(0u, i0 + 2u), i0 + 2u);
        unsigned long long k3 = enc_from_bits(threefry_bits_key01(0u, i0 + 3u), i0 + 3u);
        k0 = m.x ? k0 : 0ULL;                  // SELs, no branches
        k1 = m.y ? k1 : 0ULL;
        k2 = m.z ? k2 : 0ULL;
        k3 = m.w ? k3 : 0ULL;
        best = u64max(u64max(k0, k1), u64max(k2, k3));
        cnt  = m.x + m.y + m.z + m.w;          // mask words are exactly 0/1
    }
    // tail (n % 4 != 0 only; N=100000 -> dead, kept for generality)
    if (gi < (n & 3)) {
        uint32_t i = (uint32_t)((n4 << 2) + gi);
        if (v[i]) { cnt++; best = u64max(best, enc_from_bits(threefry_bits_key01(0u, i), i)); }
    }

    // ---- warp reduction ----
    cnt = __reduce_add_sync(0xFFFFFFFFu, (unsigned)cnt);
    #pragma unroll
    for (int off = 16; off > 0; off >>= 1)
        best = u64max(best, __shfl_xor_sync(0xFFFFFFFFu, best, off));

    // ---- cross-warp: 8 warps -> warp 0 ----
    __shared__ unsigned long long sk[8];
    __shared__ int                sc[8];
    const int warp = tid >> 5, lane = tid & 31;
    if (lane == 0) { sk[warp] = best; sc[warp] = cnt; }
    __syncthreads();
    if (warp == 0) {
        best = (lane < 8) ? sk[lane] : 0ULL;
        cnt  = (lane < 8) ? sc[lane] : 0;
        cnt  = __reduce_add_sync(0xFFFFFFFFu, (unsigned)cnt);
        #pragma unroll
        for (int off = 4; off > 0; off >>= 1)
            best = u64max(best, __shfl_xor_sync(0xFFFFFFFFu, best, off));

        if (lane == 0) {
            atomicMax(&g_best, best);              // result unused -> REDG.MAX
            atomicAdd(&g_count, (unsigned)cnt);    // result unused -> REDG.ADD
            __threadfence();                       // release before done++
            unsigned int t = atomicAdd(&g_done, 1u);
            if (t == (unsigned int)(nblocks - 1)) {
                __threadfence();                   // acquire
                // two independent volatile loads (overlapped, ~260cyc total)
                unsigned long long fb = *(volatile unsigned long long*)&g_best;
                unsigned int       fc = *(volatile unsigned int*)&g_count;
                uint32_t choice = 0xFFFFFFFFu - (uint32_t)(fb & 0xFFFFFFFFu);
                out[0] = (float)choice;
                out[1] = -__logf((float)(fc > 0u ? fc : 1u));
                g_best  = 0ULL;                    // reset for next graph replay
                g_count = 0u;
                g_done  = 0u;
            }
        }
    }
}

extern "C" void kernel_launch(void* const* d_in, const int* in_sizes, int n_in,
                              void* d_out, int out_size) {
    // inputs: ... 9 = valid_mask (int32), 10 = current_node
    const int* valid = (const int*)d_in[9];
    int n = in_sizes[9];                       // N = 100000
    int n4 = n >> 2;
    int threads = 256;
    int blocks = (n4 + threads - 1) / threads; // 98 for N=100000
    if (blocks < 1) blocks = 1;
    decide_kernel<<<blocks, threads>>>((const int4*)valid, valid,
                                       (float*)d_out, n, blocks);
}